// round 1
// baseline (speedup 1.0000x reference)
#include <cuda_runtime.h>
#include <math.h>

#define Bb   2
#define Tt   2048
#define HIDD 2048
#define NH   16
#define KVH  4
#define HD   128
#define Mrows (Bb*Tt)

// ---------------- scratch (device globals: allocation-free) ----------------
__device__ float g_Q[(size_t)Bb*NH*Tt*HD];    // [B, NH, T, HD]
__device__ float g_K[(size_t)Bb*KVH*Tt*HD];   // [B, KVH, T, HD]
__device__ float g_V[(size_t)Bb*KVH*Tt*HD];   // [B, KVH, T, HD]
__device__ float g_ctx[(size_t)Bb*Tt*HIDD];   // [B*T, HID]

// ---------------- SGEMM: C = A[M,K] @ W[K,N] ----------------
// 64x64 block tile, BK=16, 256 threads, 4x4 microtile.
// mode 0: C row-major [M,N].  mode 1: C as [B, H, T, HD] head layout.
#define BM 64
#define BN 64
#define BK 16

__global__ __launch_bounds__(256) void sgemm_kernel(
    const float* __restrict__ A, const float* __restrict__ W,
    float* __restrict__ C, int N, int K, int mode, int H)
{
    __shared__ float As[BK][72];   // transposed A tile, padded
    __shared__ float Bs[BK][BN];

    int tid = threadIdx.x;
    int tx = tid & 15, ty = tid >> 4;
    int m0 = blockIdx.y * BM, n0 = blockIdx.x * BN;

    int arow = tid >> 2;              // 0..63
    int acol = (tid & 3) << 2;        // 0,4,8,12
    int brow = tid >> 4;              // 0..15
    int bcol = (tid & 15) << 2;       // 0..60

    const float* Aptr = A + (size_t)(m0 + arow) * K + acol;
    const float* Wptr = W + (size_t)brow * N + n0 + bcol;

    float acc[4][4] = {};

    for (int k0 = 0; k0 < K; k0 += BK) {
        float4 av = *(const float4*)(Aptr + k0);
        float4 bv = *(const float4*)(Wptr + (size_t)k0 * N);
        As[acol+0][arow] = av.x;
        As[acol+1][arow] = av.y;
        As[acol+2][arow] = av.z;
        As[acol+3][arow] = av.w;
        *(float4*)&Bs[brow][bcol] = bv;
        __syncthreads();

        #pragma unroll
        for (int kk = 0; kk < BK; ++kk) {
            float a[4], b[4];
            *(float4*)a = *(const float4*)&As[kk][ty << 2];
            *(float4*)b = *(const float4*)&Bs[kk][tx << 2];
            #pragma unroll
            for (int i = 0; i < 4; ++i)
                #pragma unroll
                for (int j = 0; j < 4; ++j)
                    acc[i][j] += a[i] * b[j];
        }
        __syncthreads();
    }

    if (mode == 0) {
        #pragma unroll
        for (int i = 0; i < 4; ++i) {
            int m = m0 + (ty << 2) + i;
            float4 v = make_float4(acc[i][0], acc[i][1], acc[i][2], acc[i][3]);
            *(float4*)&C[(size_t)m * N + n0 + (tx << 2)] = v;
        }
    } else {
        // n0 is a multiple of 64; 64 cols stay inside one 128-wide head
        int h = n0 >> 7;
        int dbase = (n0 & 127) + (tx << 2);
        #pragma unroll
        for (int i = 0; i < 4; ++i) {
            int m = m0 + (ty << 2) + i;
            int b = m >> 11;           // /Tt
            int t = m & (Tt - 1);
            float4 v = make_float4(acc[i][0], acc[i][1], acc[i][2], acc[i][3]);
            *(float4*)&C[(((size_t)(b * H + h) * Tt + t) << 7) + dbase] = v;
        }
    }
}

// ---------------- RoPE (in-place on [B,H,T,HD]) ----------------
__global__ void rope_kernel(float* __restrict__ X, const float* __restrict__ cs,
                            const float* __restrict__ sn, int total)
{
    int i = blockIdx.x * blockDim.x + threadIdx.x;
    if (i >= total) return;
    int d = i & 63;
    int rest = i >> 6;               // (b*H+h)*T + t
    int t = rest & (Tt - 1);
    float* row = X + ((size_t)rest << 7);
    float x1 = row[d], x2 = row[d + 64];
    float c1 = cs[(t << 7) + d],      s1 = sn[(t << 7) + d];
    float c2 = cs[(t << 7) + d + 64], s2 = sn[(t << 7) + d + 64];
    row[d]      = x1 * c1 - x2 * s1;
    row[d + 64] = x2 * c2 + x1 * s2;
}

// ---------------- Flash attention (causal, GQA) ----------------
// One block per (q-tile of 64, b*NH+h). 256 threads.
// smem: Qs/Ks/Vs [64][132], Ss [64][68], stats [3*64].
#define QKV_STRIDE 132
#define SS_STRIDE  68

__global__ __launch_bounds__(256) void flash_kernel(
    const float* __restrict__ Q, const float* __restrict__ K,
    const float* __restrict__ V, float* __restrict__ ctx)
{
    extern __shared__ float sm[];
    float* Qs   = sm;
    float* Ks   = Qs + 64 * QKV_STRIDE;
    float* Vs   = Ks + 64 * QKV_STRIDE;
    float* Ss   = Vs + 64 * QKV_STRIDE;
    float* mrow = Ss + 64 * SS_STRIDE;
    float* lrow = mrow + 64;
    float* crow = lrow + 64;

    int tid = threadIdx.x;
    int tx = tid & 15, ty = tid >> 4;
    int qt = blockIdx.x;
    int bh = blockIdx.y;
    int b = bh >> 4;        // / NH
    int h = bh & 15;
    int kvh = h >> 2;       // NH/KVH = 4

    const float* Qp = Q + (((size_t)(b * NH + h) * Tt + qt * 64) << 7);
    const float* Kp = K + (((size_t)(b * KVH + kvh) * Tt) << 7);
    const float* Vp = V + (((size_t)(b * KVH + kvh) * Tt) << 7);

    // load Q tile (coalesced; conflict-free f4 smem writes at stride 33 f4)
    #pragma unroll
    for (int r = 0; r < 8; ++r) {
        int e = tid + r * 256;
        int row = e >> 5, d4 = (e & 31) << 2;
        *(float4*)(Qs + row * QKV_STRIDE + d4) = *(const float4*)(Qp + (row << 7) + d4);
    }
    if (tid < 64) { mrow[tid] = -1e30f; lrow[tid] = 0.f; }

    float o[4][8];
    #pragma unroll
    for (int i = 0; i < 4; ++i)
        #pragma unroll
        for (int d = 0; d < 8; ++d) o[i][d] = 0.f;

    const float scale = 0.08838834764831845f;  // 1/sqrt(128)

    for (int kt = 0; kt <= qt; ++kt) {
        __syncthreads();   // prev PV done (and Q/stats init on first iter)
        const float* kp = Kp + ((size_t)kt << 13);
        const float* vp = Vp + ((size_t)kt << 13);
        #pragma unroll
        for (int r = 0; r < 8; ++r) {
            int e = tid + r * 256;
            int row = e >> 5, d4 = (e & 31) << 2;
            *(float4*)(Ks + row * QKV_STRIDE + d4) = *(const float4*)(kp + (row << 7) + d4);
            *(float4*)(Vs + row * QKV_STRIDE + d4) = *(const float4*)(vp + (row << 7) + d4);
        }
        __syncthreads();

        // ---- S = scale * Q K^T (4x4 microtile per thread) ----
        float s[4][4] = {};
        #pragma unroll 4
        for (int d4 = 0; d4 < 128; d4 += 4) {
            float qa[4][4], ka[4][4];
            #pragma unroll
            for (int i = 0; i < 4; ++i)
                *(float4*)qa[i] = *(const float4*)(Qs + (ty * 4 + i) * QKV_STRIDE + d4);
            #pragma unroll
            for (int j = 0; j < 4; ++j)
                *(float4*)ka[j] = *(const float4*)(Ks + (tx * 4 + j) * QKV_STRIDE + d4);
            #pragma unroll
            for (int i = 0; i < 4; ++i)
                #pragma unroll
                for (int j = 0; j < 4; ++j)
                    #pragma unroll
                    for (int c = 0; c < 4; ++c)
                        s[i][j] += qa[i][c] * ka[j][c];
        }

        bool diag = (kt == qt);
        #pragma unroll
        for (int i = 0; i < 4; ++i) {
            float row4[4];
            #pragma unroll
            for (int j = 0; j < 4; ++j) {
                float val = s[i][j] * scale;
                if (diag && (tx * 4 + j > ty * 4 + i)) val = -1e30f;
                row4[j] = val;
            }
            *(float4*)&Ss[(ty * 4 + i) * SS_STRIDE + tx * 4] = *(float4*)row4;
        }
        __syncthreads();

        // ---- online softmax (4 threads per row) ----
        {
            int r = tid >> 2, c = tid & 3;
            float* srow = Ss + r * SS_STRIDE + c * 16;
            float tm = -1e30f;
            #pragma unroll
            for (int jj = 0; jj < 16; ++jj) tm = fmaxf(tm, srow[jj]);
            tm = fmaxf(tm, __shfl_xor_sync(0xffffffffu, tm, 1));
            tm = fmaxf(tm, __shfl_xor_sync(0xffffffffu, tm, 2));
            float mold = mrow[r];
            float mnew = fmaxf(mold, tm);
            float ps = 0.f;
            #pragma unroll
            for (int jj = 0; jj < 16; ++jj) {
                float p = __expf(srow[jj] - mnew);
                srow[jj] = p;
                ps += p;
            }
            ps += __shfl_xor_sync(0xffffffffu, ps, 1);
            ps += __shfl_xor_sync(0xffffffffu, ps, 2);
            if (c == 0) {
                float corr = __expf(mold - mnew);
                mrow[r] = mnew;
                lrow[r] = lrow[r] * corr + ps;
                crow[r] = corr;
            }
        }
        __syncthreads();

        // ---- rescale O, accumulate P @ V ----
        float cr[4];
        #pragma unroll
        for (int i = 0; i < 4; ++i) cr[i] = crow[ty * 4 + i];
        #pragma unroll
        for (int i = 0; i < 4; ++i)
            #pragma unroll
            for (int d = 0; d < 8; ++d) o[i][d] *= cr[i];

        #pragma unroll 4
        for (int j = 0; j < 64; ++j) {
            float vv[8];
            *(float4*)vv       = *(const float4*)(Vs + j * QKV_STRIDE + tx * 8);
            *(float4*)(vv + 4) = *(const float4*)(Vs + j * QKV_STRIDE + tx * 8 + 4);
            #pragma unroll
            for (int i = 0; i < 4; ++i) {
                float p = Ss[(ty * 4 + i) * SS_STRIDE + j];
                #pragma unroll
                for (int d = 0; d < 8; ++d) o[i][d] += p * vv[d];
            }
        }
    }

    // ---- finalize: O /= l, write ctx[b*T+t, h*HD+d] ----
    #pragma unroll
    for (int i = 0; i < 4; ++i) {
        float linv = 1.0f / lrow[ty * 4 + i];
        int t = qt * 64 + ty * 4 + i;
        float* dst = ctx + (size_t)(b * Tt + t) * HIDD + h * HD + tx * 8;
        float4 w0 = make_float4(o[i][0]*linv, o[i][1]*linv, o[i][2]*linv, o[i][3]*linv);
        float4 w1 = make_float4(o[i][4]*linv, o[i][5]*linv, o[i][6]*linv, o[i][7]*linv);
        *(float4*)dst       = w0;
        *(float4*)(dst + 4) = w1;
    }
}

// ---------------- launch ----------------
extern "C" void kernel_launch(void* const* d_in, const int* in_sizes, int n_in,
                              void* d_out, int out_size)
{
    const float* hs   = (const float*)d_in[0];
    // d_in[1] = attention_mask (standard causal -1e9): handled analytically
    const float* cosp = (const float*)d_in[2];
    const float* sinp = (const float*)d_in[3];
    const float* Wq   = (const float*)d_in[4];
    const float* Wk   = (const float*)d_in[5];
    const float* Wv   = (const float*)d_in[6];
    const float* Wo   = (const float*)d_in[7];
    float* out = (float*)d_out;

    float *pQ, *pK, *pV, *pC;
    cudaGetSymbolAddress((void**)&pQ, g_Q);
    cudaGetSymbolAddress((void**)&pK, g_K);
    cudaGetSymbolAddress((void**)&pV, g_V);
    cudaGetSymbolAddress((void**)&pC, g_ctx);

    // QKV projections (head-layout epilogue)
    sgemm_kernel<<<dim3((NH*HD)/BN,  Mrows/BM), 256>>>(hs, Wq, pQ, NH*HD,  HIDD, 1, NH);
    sgemm_kernel<<<dim3((KVH*HD)/BN, Mrows/BM), 256>>>(hs, Wk, pK, KVH*HD, HIDD, 1, KVH);
    sgemm_kernel<<<dim3((KVH*HD)/BN, Mrows/BM), 256>>>(hs, Wv, pV, KVH*HD, HIDD, 1, KVH);

    // RoPE on Q and K
    int totQ = Bb * NH  * Tt * 64;
    int totK = Bb * KVH * Tt * 64;
    rope_kernel<<<totQ / 256, 256>>>(pQ, cosp, sinp, totQ);
    rope_kernel<<<totK / 256, 256>>>(pK, cosp, sinp, totK);

    // Flash attention
    size_t shmem = (size_t)(3 * 64 * QKV_STRIDE + 64 * SS_STRIDE + 3 * 64) * sizeof(float);
    cudaFuncSetAttribute(flash_kernel, cudaFuncAttributeMaxDynamicSharedMemorySize, (int)shmem);
    flash_kernel<<<dim3(Tt/64, Bb*NH), 256, shmem>>>(pQ, pK, pV, pC);

    // Output projection -> d_out
    sgemm_kernel<<<dim3(HIDD/BN, Mrows/BM), 256>>>(pC, Wo, out, HIDD, HIDD, 0, 0);
}

// round 4
// speedup vs baseline: 1.5582x; 1.5582x over previous
#include <cuda_runtime.h>
#include <cuda_bf16.h>
#include <cstdint>
#include <math.h>

#define Bb   2
#define Tt   2048
#define HIDD 2048
#define NH   16
#define KVH  4
#define HD   128
#define Mrows (Bb*Tt)

// ---------------- scratch (device globals: allocation-free) ----------------
__device__ float g_Q[(size_t)Bb*NH*Tt*HD];    // [B, NH, T, HD]
__device__ float g_K[(size_t)Bb*KVH*Tt*HD];   // [B, KVH, T, HD]
__device__ float g_V[(size_t)Bb*KVH*Tt*HD];   // [B, KVH, T, HD]
__device__ float g_ctx[(size_t)Bb*Tt*HIDD];   // [B*T, HID]

// ================= mma.sync helpers (compute_103-safe) =====================
__device__ __forceinline__ uint32_t smem_u32(const void* p) {
    uint32_t a;
    asm("{ .reg .u64 t; cvta.to.shared.u64 t, %1; cvt.u32.u64 %0, t; }" : "=r"(a) : "l"(p));
    return a;
}
__device__ __forceinline__ void ldm_x4(uint32_t& r0, uint32_t& r1, uint32_t& r2,
                                       uint32_t& r3, uint32_t addr) {
    asm volatile("ldmatrix.sync.aligned.m8n8.x4.shared.b16 {%0,%1,%2,%3}, [%4];"
                 : "=r"(r0), "=r"(r1), "=r"(r2), "=r"(r3) : "r"(addr));
}
__device__ __forceinline__ void ldm_x4_trans(uint32_t& r0, uint32_t& r1, uint32_t& r2,
                                             uint32_t& r3, uint32_t addr) {
    asm volatile("ldmatrix.sync.aligned.m8n8.x4.trans.shared.b16 {%0,%1,%2,%3}, [%4];"
                 : "=r"(r0), "=r"(r1), "=r"(r2), "=r"(r3) : "r"(addr));
}
__device__ __forceinline__ void mma16816(float* c, uint32_t a0, uint32_t a1,
                                         uint32_t a2, uint32_t a3,
                                         uint32_t b0, uint32_t b1) {
    asm volatile(
        "mma.sync.aligned.m16n8k16.row.col.f32.bf16.bf16.f32 "
        "{%0,%1,%2,%3}, {%4,%5,%6,%7}, {%8,%9}, {%0,%1,%2,%3};"
        : "+f"(c[0]), "+f"(c[1]), "+f"(c[2]), "+f"(c[3])
        : "r"(a0), "r"(a1), "r"(a2), "r"(a3), "r"(b0), "r"(b1));
}

// ======== mma.sync GEMM: C[M,N] = A[M,K] @ W[K,N], bf16 hi/lo split ========
// Tile 128x128, BK=32, 256 threads, 8 warps in 2(M)x4(N), warp tile 64x32.
// A smem: [m][k] rows of 40 bf16 (80B, 16B-aligned, ldmatrix conflict-free).
// B smem: [k][n] rows of 136 bf16 (272B, 16B-aligned), read via ldmatrix.trans.
// mode 0: C row-major [M,N].  mode 1: C as [B, H, T, HD] head layout.
#define SP  40
#define BSP 136

__device__ __forceinline__ void split4(float4 v, uint32_t& h0, uint32_t& h1,
                                       uint32_t& l0, uint32_t& l1) {
    __nv_bfloat162 a = __floats2bfloat162_rn(v.x, v.y);
    __nv_bfloat162 b = __floats2bfloat162_rn(v.z, v.w);
    __nv_bfloat162 ra = __floats2bfloat162_rn(v.x - __bfloat162float(a.x),
                                              v.y - __bfloat162float(a.y));
    __nv_bfloat162 rb = __floats2bfloat162_rn(v.z - __bfloat162float(b.x),
                                              v.w - __bfloat162float(b.y));
    h0 = *(uint32_t*)&a; h1 = *(uint32_t*)&b;
    l0 = *(uint32_t*)&ra; l1 = *(uint32_t*)&rb;
}

__global__ __launch_bounds__(256, 2) void tc_gemm_kernel(
    const float* __restrict__ A, const float* __restrict__ W,
    float* __restrict__ C, int N, int K, int mode, int H)
{
    __shared__ __align__(16) uint16_t sAh[128 * SP];
    __shared__ __align__(16) uint16_t sAl[128 * SP];
    __shared__ __align__(16) uint16_t sBh[32 * BSP];
    __shared__ __align__(16) uint16_t sBl[32 * BSP];

    const uint32_t uAh = smem_u32(sAh), uAl = smem_u32(sAl);
    const uint32_t uBh = smem_u32(sBh), uBl = smem_u32(sBl);

    int tid = threadIdx.x;
    int wid = tid >> 5, lane = tid & 31;
    int wm = wid >> 2, wn = wid & 3;          // warp grid 2x4
    int m0 = blockIdx.y << 7, n0 = blockIdx.x << 7;

    // global-load mappings
    int arow = tid >> 1;                      // 0..127
    int acb  = (tid & 1) << 4;                // 0 or 16
    int bk0  = tid >> 5;                      // 0..7 (k row base)
    int bn4  = (tid & 31) << 2;               // 0..124 (n group of 4)

    const float* apg = A + (size_t)(m0 + arow) * K + acb;
    const float* bpg = W + (size_t)bk0 * N + n0 + bn4;

    float acc[4][4][4];
    #pragma unroll
    for (int i = 0; i < 4; ++i)
        #pragma unroll
        for (int j = 0; j < 4; ++j)
            #pragma unroll
            for (int e = 0; e < 4; ++e) acc[i][j][e] = 0.f;

    for (int k0 = 0; k0 < K; k0 += 32) {
        // ---- stage A: [128 m][32 k] fp32 -> bf16 hi/lo ----
        #pragma unroll
        for (int c = 0; c < 4; ++c) {
            float4 v = *(const float4*)(apg + k0 + (c << 2));
            uint32_t h0, h1, l0, l1;
            split4(v, h0, h1, l0, l1);
            uint32_t off = (uint32_t)(arow * SP + acb + (c << 2)) << 1;
            *(uint32_t*)((char*)sAh + off)     = h0;
            *(uint32_t*)((char*)sAh + off + 4) = h1;
            *(uint32_t*)((char*)sAl + off)     = l0;
            *(uint32_t*)((char*)sAl + off + 4) = l1;
        }
        // ---- stage B: [32 k][128 n], natural layout (no transpose) ----
        #pragma unroll
        for (int it = 0; it < 4; ++it) {
            float4 v = *(const float4*)(bpg + (size_t)(k0 + (it << 3)) * N);
            uint32_t h0, h1, l0, l1;
            split4(v, h0, h1, l0, l1);   // pairs along n
            uint32_t off = (uint32_t)((bk0 + (it << 3)) * BSP + bn4) << 1;
            *(uint32_t*)((char*)sBh + off)     = h0;
            *(uint32_t*)((char*)sBh + off + 4) = h1;
            *(uint32_t*)((char*)sBl + off)     = l0;
            *(uint32_t*)((char*)sBl + off + 4) = l1;
        }
        __syncthreads();

        // ---- compute: 2 k16 steps ----
        int r16 = lane & 15, hsel = lane >> 4;      // row-in-16, half-select
        #pragma unroll
        for (int ks = 0; ks < 2; ++ks) {
            // B: one x4.trans per 16-n chunk gives (k-lo/n-lo, k-hi/n-lo, k-lo/n-hi, k-hi/n-hi)
            uint32_t bh[2][4], bl[2][4];
            #pragma unroll
            for (int j2 = 0; j2 < 2; ++j2) {
                uint32_t boff = (uint32_t)((ks * 16 + r16) * BSP +
                                           (wn << 5) + (j2 << 4) + (hsel << 3)) << 1;
                ldm_x4_trans(bh[j2][0], bh[j2][1], bh[j2][2], bh[j2][3], uBh + boff);
                ldm_x4_trans(bl[j2][0], bl[j2][1], bl[j2][2], bl[j2][3], uBl + boff);
            }
            #pragma unroll
            for (int i = 0; i < 4; ++i) {
                uint32_t aoff = (uint32_t)(((wm << 6) + (i << 4) + r16) * SP +
                                           ks * 16 + (hsel << 3)) << 1;
                uint32_t ah0, ah1, ah2, ah3, al0, al1, al2, al3;
                ldm_x4(ah0, ah1, ah2, ah3, uAh + aoff);
                ldm_x4(al0, al1, al2, al3, uAl + aoff);
                #pragma unroll
                for (int j2 = 0; j2 < 2; ++j2) {
                    // hi*hi
                    mma16816(acc[i][2*j2],   ah0, ah1, ah2, ah3, bh[j2][0], bh[j2][1]);
                    mma16816(acc[i][2*j2+1], ah0, ah1, ah2, ah3, bh[j2][2], bh[j2][3]);
                    // hi*lo
                    mma16816(acc[i][2*j2],   ah0, ah1, ah2, ah3, bl[j2][0], bl[j2][1]);
                    mma16816(acc[i][2*j2+1], ah0, ah1, ah2, ah3, bl[j2][2], bl[j2][3]);
                    // lo*hi
                    mma16816(acc[i][2*j2],   al0, al1, al2, al3, bh[j2][0], bh[j2][1]);
                    mma16816(acc[i][2*j2+1], al0, al1, al2, al3, bh[j2][2], bh[j2][3]);
                }
            }
        }
        __syncthreads();
    }

    // ---- epilogue ----
    int g = lane >> 2, q = lane & 3;
    #pragma unroll
    for (int i = 0; i < 4; ++i) {
        #pragma unroll
        for (int half = 0; half < 2; ++half) {
            int m = m0 + (wm << 6) + (i << 4) + g + (half << 3);
            float* dst;
            if (mode == 0) {
                dst = C + (size_t)m * N + n0;
            } else {
                int b = m >> 11, t = m & (Tt - 1), h = n0 >> 7;
                dst = C + (((size_t)(b * H + h) * Tt + t) << 7);
            }
            #pragma unroll
            for (int j = 0; j < 4; ++j) {
                int nl = (wn << 5) + (j << 3) + (q << 1);
                float2 v;
                v.x = acc[i][j][half * 2];
                v.y = acc[i][j][half * 2 + 1];
                *(float2*)(dst + nl) = v;
            }
        }
    }
}

// ---------------- RoPE (in-place on [B,H,T,HD]) ----------------
__global__ void rope_kernel(float* __restrict__ X, const float* __restrict__ cs,
                            const float* __restrict__ sn, int total)
{
    int i = blockIdx.x * blockDim.x + threadIdx.x;
    if (i >= total) return;
    int d = i & 63;
    int rest = i >> 6;
    int t = rest & (Tt - 1);
    float* row = X + ((size_t)rest << 7);
    float x1 = row[d], x2 = row[d + 64];
    float c1 = cs[(t << 7) + d],      s1 = sn[(t << 7) + d];
    float c2 = cs[(t << 7) + d + 64], s2 = sn[(t << 7) + d + 64];
    row[d]      = x1 * c1 - x2 * s1;
    row[d + 64] = x2 * c2 + x1 * s2;
}

// ---------------- Flash attention (causal, GQA) — fp32 SIMT ----------------
#define QKV_STRIDE 132
#define SS_STRIDE  68

__global__ __launch_bounds__(256) void flash_kernel(
    const float* __restrict__ Q, const float* __restrict__ K,
    const float* __restrict__ V, float* __restrict__ ctx)
{
    extern __shared__ float sm[];
    float* Qs   = sm;
    float* Ks   = Qs + 64 * QKV_STRIDE;
    float* Vs   = Ks + 64 * QKV_STRIDE;
    float* Ss   = Vs + 64 * QKV_STRIDE;
    float* mrow = Ss + 64 * SS_STRIDE;
    float* lrow = mrow + 64;
    float* crow = lrow + 64;

    int tid = threadIdx.x;
    int tx = tid & 15, ty = tid >> 4;
    int qt = blockIdx.x;
    int bh = blockIdx.y;
    int b = bh >> 4;
    int h = bh & 15;
    int kvh = h >> 2;

    const float* Qp = Q + (((size_t)(b * NH + h) * Tt + qt * 64) << 7);
    const float* Kp = K + (((size_t)(b * KVH + kvh) * Tt) << 7);
    const float* Vp = V + (((size_t)(b * KVH + kvh) * Tt) << 7);

    #pragma unroll
    for (int r = 0; r < 8; ++r) {
        int e = tid + r * 256;
        int row = e >> 5, d4 = (e & 31) << 2;
        *(float4*)(Qs + row * QKV_STRIDE + d4) = *(const float4*)(Qp + (row << 7) + d4);
    }
    if (tid < 64) { mrow[tid] = -1e30f; lrow[tid] = 0.f; }

    float o[4][8];
    #pragma unroll
    for (int i = 0; i < 4; ++i)
        #pragma unroll
        for (int d = 0; d < 8; ++d) o[i][d] = 0.f;

    const float scale = 0.08838834764831845f;

    for (int kt = 0; kt <= qt; ++kt) {
        __syncthreads();
        const float* kp = Kp + ((size_t)kt << 13);
        const float* vp = Vp + ((size_t)kt << 13);
        #pragma unroll
        for (int r = 0; r < 8; ++r) {
            int e = tid + r * 256;
            int row = e >> 5, d4 = (e & 31) << 2;
            *(float4*)(Ks + row * QKV_STRIDE + d4) = *(const float4*)(kp + (row << 7) + d4);
            *(float4*)(Vs + row * QKV_STRIDE + d4) = *(const float4*)(vp + (row << 7) + d4);
        }
        __syncthreads();

        float s[4][4] = {};
        #pragma unroll 4
        for (int d4 = 0; d4 < 128; d4 += 4) {
            float qa[4][4], ka[4][4];
            #pragma unroll
            for (int i = 0; i < 4; ++i)
                *(float4*)qa[i] = *(const float4*)(Qs + (ty * 4 + i) * QKV_STRIDE + d4);
            #pragma unroll
            for (int j = 0; j < 4; ++j)
                *(float4*)ka[j] = *(const float4*)(Ks + (tx * 4 + j) * QKV_STRIDE + d4);
            #pragma unroll
            for (int i = 0; i < 4; ++i)
                #pragma unroll
                for (int j = 0; j < 4; ++j)
                    #pragma unroll
                    for (int c = 0; c < 4; ++c)
                        s[i][j] += qa[i][c] * ka[j][c];
        }

        bool diag = (kt == qt);
        #pragma unroll
        for (int i = 0; i < 4; ++i) {
            float row4[4];
            #pragma unroll
            for (int j = 0; j < 4; ++j) {
                float val = s[i][j] * scale;
                if (diag && (tx * 4 + j > ty * 4 + i)) val = -1e30f;
                row4[j] = val;
            }
            *(float4*)&Ss[(ty * 4 + i) * SS_STRIDE + tx * 4] = *(float4*)row4;
        }
        __syncthreads();

        {
            int r = tid >> 2, c = tid & 3;
            float* srow = Ss + r * SS_STRIDE + c * 16;
            float tm = -1e30f;
            #pragma unroll
            for (int jj = 0; jj < 16; ++jj) tm = fmaxf(tm, srow[jj]);
            tm = fmaxf(tm, __shfl_xor_sync(0xffffffffu, tm, 1));
            tm = fmaxf(tm, __shfl_xor_sync(0xffffffffu, tm, 2));
            float mold = mrow[r];
            float mnew = fmaxf(mold, tm);
            float ps = 0.f;
            #pragma unroll
            for (int jj = 0; jj < 16; ++jj) {
                float p = __expf(srow[jj] - mnew);
                srow[jj] = p;
                ps += p;
            }
            ps += __shfl_xor_sync(0xffffffffu, ps, 1);
            ps += __shfl_xor_sync(0xffffffffu, ps, 2);
            if (c == 0) {
                float corr = __expf(mold - mnew);
                mrow[r] = mnew;
                lrow[r] = lrow[r] * corr + ps;
                crow[r] = corr;
            }
        }
        __syncthreads();

        float cr[4];
        #pragma unroll
        for (int i = 0; i < 4; ++i) cr[i] = crow[ty * 4 + i];
        #pragma unroll
        for (int i = 0; i < 4; ++i)
            #pragma unroll
            for (int d = 0; d < 8; ++d) o[i][d] *= cr[i];

        #pragma unroll 4
        for (int j = 0; j < 64; ++j) {
            float vv[8];
            *(float4*)vv       = *(const float4*)(Vs + j * QKV_STRIDE + tx * 8);
            *(float4*)(vv + 4) = *(const float4*)(Vs + j * QKV_STRIDE + tx * 8 + 4);
            #pragma unroll
            for (int i = 0; i < 4; ++i) {
                float p = Ss[(ty * 4 + i) * SS_STRIDE + j];
                #pragma unroll
                for (int d = 0; d < 8; ++d) o[i][d] += p * vv[d];
            }
        }
    }

    #pragma unroll
    for (int i = 0; i < 4; ++i) {
        float linv = 1.0f / lrow[ty * 4 + i];
        int t = qt * 64 + ty * 4 + i;
        float* dst = ctx + (size_t)(b * Tt + t) * HIDD + h * HD + tx * 8;
        float4 w0 = make_float4(o[i][0]*linv, o[i][1]*linv, o[i][2]*linv, o[i][3]*linv);
        float4 w1 = make_float4(o[i][4]*linv, o[i][5]*linv, o[i][6]*linv, o[i][7]*linv);
        *(float4*)dst       = w0;
        *(float4*)(dst + 4) = w1;
    }
}

// ---------------- launch ----------------
extern "C" void kernel_launch(void* const* d_in, const int* in_sizes, int n_in,
                              void* d_out, int out_size)
{
    const float* hs   = (const float*)d_in[0];
    const float* cosp = (const float*)d_in[2];
    const float* sinp = (const float*)d_in[3];
    const float* Wq   = (const float*)d_in[4];
    const float* Wk   = (const float*)d_in[5];
    const float* Wv   = (const float*)d_in[6];
    const float* Wo   = (const float*)d_in[7];
    float* out = (float*)d_out;

    float *pQ, *pK, *pV, *pC;
    cudaGetSymbolAddress((void**)&pQ, g_Q);
    cudaGetSymbolAddress((void**)&pK, g_K);
    cudaGetSymbolAddress((void**)&pV, g_V);
    cudaGetSymbolAddress((void**)&pC, g_ctx);

    // QKV projections on mma.sync bf16 hi/lo
    tc_gemm_kernel<<<dim3(16, 32), 256>>>(hs, Wq, pQ, NH*HD,  HIDD, 1, NH);
    tc_gemm_kernel<<<dim3(4,  32), 256>>>(hs, Wk, pK, KVH*HD, HIDD, 1, KVH);
    tc_gemm_kernel<<<dim3(4,  32), 256>>>(hs, Wv, pV, KVH*HD, HIDD, 1, KVH);

    // RoPE on Q and K
    int totQ = Bb * NH  * Tt * 64;
    int totK = Bb * KVH * Tt * 64;
    rope_kernel<<<totQ / 256, 256>>>(pQ, cosp, sinp, totQ);
    rope_kernel<<<totK / 256, 256>>>(pK, cosp, sinp, totK);

    // Flash attention (fp32 SIMT)
    size_t shmem = (size_t)(3 * 64 * QKV_STRIDE + 64 * SS_STRIDE + 3 * 64) * sizeof(float);
    cudaFuncSetAttribute(flash_kernel, cudaFuncAttributeMaxDynamicSharedMemorySize, (int)shmem);
    flash_kernel<<<dim3(Tt/64, Bb*NH), 256, shmem>>>(pQ, pK, pV, pC);

    // Output projection -> d_out
    tc_gemm_kernel<<<dim3(16, 32), 256>>>(pC, Wo, out, HIDD, HIDD, 0, 0);
}

// round 5
// speedup vs baseline: 3.0844x; 1.9794x over previous
#include <cuda_runtime.h>
#include <cuda_bf16.h>
#include <cstdint>
#include <math.h>

#define Bb   2
#define Tt   2048
#define HIDD 2048
#define NH   16
#define KVH  4
#define HD   128
#define Mrows (Bb*Tt)

// ---------------- scratch (device globals: allocation-free) ----------------
__device__ float g_Q[(size_t)Bb*NH*Tt*HD];    // [B, NH, T, HD]
__device__ float g_K[(size_t)Bb*KVH*Tt*HD];   // [B, KVH, T, HD]
__device__ float g_V[(size_t)Bb*KVH*Tt*HD];   // [B, KVH, T, HD]
__device__ float g_ctx[(size_t)Bb*Tt*HIDD];   // [B*T, HID]

// ================= mma.sync helpers (compute_103-safe) =====================
__device__ __forceinline__ uint32_t smem_u32(const void* p) {
    uint32_t a;
    asm("{ .reg .u64 t; cvta.to.shared.u64 t, %1; cvt.u32.u64 %0, t; }" : "=r"(a) : "l"(p));
    return a;
}
__device__ __forceinline__ void ldm_x4(uint32_t& r0, uint32_t& r1, uint32_t& r2,
                                       uint32_t& r3, uint32_t addr) {
    asm volatile("ldmatrix.sync.aligned.m8n8.x4.shared.b16 {%0,%1,%2,%3}, [%4];"
                 : "=r"(r0), "=r"(r1), "=r"(r2), "=r"(r3) : "r"(addr));
}
__device__ __forceinline__ void ldm_x4_trans(uint32_t& r0, uint32_t& r1, uint32_t& r2,
                                             uint32_t& r3, uint32_t addr) {
    asm volatile("ldmatrix.sync.aligned.m8n8.x4.trans.shared.b16 {%0,%1,%2,%3}, [%4];"
                 : "=r"(r0), "=r"(r1), "=r"(r2), "=r"(r3) : "r"(addr));
}
__device__ __forceinline__ void mma16816(float* c, uint32_t a0, uint32_t a1,
                                         uint32_t a2, uint32_t a3,
                                         uint32_t b0, uint32_t b1) {
    asm volatile(
        "mma.sync.aligned.m16n8k16.row.col.f32.bf16.bf16.f32 "
        "{%0,%1,%2,%3}, {%4,%5,%6,%7}, {%8,%9}, {%0,%1,%2,%3};"
        : "+f"(c[0]), "+f"(c[1]), "+f"(c[2]), "+f"(c[3])
        : "r"(a0), "r"(a1), "r"(a2), "r"(a3), "r"(b0), "r"(b1));
}
__device__ __forceinline__ float ex2(float x) {
    float r;
    asm("ex2.approx.f32 %0, %1;" : "=f"(r) : "f"(x));
    return r;
}

__device__ __forceinline__ void split4(float4 v, uint32_t& h0, uint32_t& h1,
                                       uint32_t& l0, uint32_t& l1) {
    __nv_bfloat162 a = __floats2bfloat162_rn(v.x, v.y);
    __nv_bfloat162 b = __floats2bfloat162_rn(v.z, v.w);
    __nv_bfloat162 ra = __floats2bfloat162_rn(v.x - __bfloat162float(a.x),
                                              v.y - __bfloat162float(a.y));
    __nv_bfloat162 rb = __floats2bfloat162_rn(v.z - __bfloat162float(b.x),
                                              v.w - __bfloat162float(b.y));
    h0 = *(uint32_t*)&a; h1 = *(uint32_t*)&b;
    l0 = *(uint32_t*)&ra; l1 = *(uint32_t*)&rb;
}
__device__ __forceinline__ uint32_t pack_hi(float x, float y) {
    __nv_bfloat162 h = __floats2bfloat162_rn(x, y);
    return *(uint32_t*)&h;
}
__device__ __forceinline__ uint32_t pack_lo(float x, float y, uint32_t hbits) {
    __nv_bfloat162 h = *(__nv_bfloat162*)&hbits;
    __nv_bfloat162 l = __floats2bfloat162_rn(x - __bfloat162float(h.x),
                                             y - __bfloat162float(h.y));
    return *(uint32_t*)&l;
}

// ======== mma.sync GEMM: C[M,N] = A[M,K] @ W[K,N], bf16 hi/lo split ========
#define SP  40
#define BSP 136

__global__ __launch_bounds__(256, 2) void tc_gemm_kernel(
    const float* __restrict__ A, const float* __restrict__ W,
    float* __restrict__ C, int N, int K, int mode, int H)
{
    __shared__ __align__(16) uint16_t sAh[128 * SP];
    __shared__ __align__(16) uint16_t sAl[128 * SP];
    __shared__ __align__(16) uint16_t sBh[32 * BSP];
    __shared__ __align__(16) uint16_t sBl[32 * BSP];

    const uint32_t uAh = smem_u32(sAh), uAl = smem_u32(sAl);
    const uint32_t uBh = smem_u32(sBh), uBl = smem_u32(sBl);

    int tid = threadIdx.x;
    int wid = tid >> 5, lane = tid & 31;
    int wm = wid >> 2, wn = wid & 3;
    int m0 = blockIdx.y << 7, n0 = blockIdx.x << 7;

    int arow = tid >> 1;
    int acb  = (tid & 1) << 4;
    int bk0  = tid >> 5;
    int bn4  = (tid & 31) << 2;

    const float* apg = A + (size_t)(m0 + arow) * K + acb;
    const float* bpg = W + (size_t)bk0 * N + n0 + bn4;

    float acc[4][4][4];
    #pragma unroll
    for (int i = 0; i < 4; ++i)
        #pragma unroll
        for (int j = 0; j < 4; ++j)
            #pragma unroll
            for (int e = 0; e < 4; ++e) acc[i][j][e] = 0.f;

    for (int k0 = 0; k0 < K; k0 += 32) {
        #pragma unroll
        for (int c = 0; c < 4; ++c) {
            float4 v = *(const float4*)(apg + k0 + (c << 2));
            uint32_t h0, h1, l0, l1;
            split4(v, h0, h1, l0, l1);
            uint32_t off = (uint32_t)(arow * SP + acb + (c << 2)) << 1;
            *(uint32_t*)((char*)sAh + off)     = h0;
            *(uint32_t*)((char*)sAh + off + 4) = h1;
            *(uint32_t*)((char*)sAl + off)     = l0;
            *(uint32_t*)((char*)sAl + off + 4) = l1;
        }
        #pragma unroll
        for (int it = 0; it < 4; ++it) {
            float4 v = *(const float4*)(bpg + (size_t)(k0 + (it << 3)) * N);
            uint32_t h0, h1, l0, l1;
            split4(v, h0, h1, l0, l1);
            uint32_t off = (uint32_t)((bk0 + (it << 3)) * BSP + bn4) << 1;
            *(uint32_t*)((char*)sBh + off)     = h0;
            *(uint32_t*)((char*)sBh + off + 4) = h1;
            *(uint32_t*)((char*)sBl + off)     = l0;
            *(uint32_t*)((char*)sBl + off + 4) = l1;
        }
        __syncthreads();

        int r16 = lane & 15, hsel = lane >> 4;
        #pragma unroll
        for (int ks = 0; ks < 2; ++ks) {
            uint32_t bh[2][4], bl[2][4];
            #pragma unroll
            for (int j2 = 0; j2 < 2; ++j2) {
                uint32_t boff = (uint32_t)((ks * 16 + r16) * BSP +
                                           (wn << 5) + (j2 << 4) + (hsel << 3)) << 1;
                ldm_x4_trans(bh[j2][0], bh[j2][1], bh[j2][2], bh[j2][3], uBh + boff);
                ldm_x4_trans(bl[j2][0], bl[j2][1], bl[j2][2], bl[j2][3], uBl + boff);
            }
            #pragma unroll
            for (int i = 0; i < 4; ++i) {
                uint32_t aoff = (uint32_t)(((wm << 6) + (i << 4) + r16) * SP +
                                           ks * 16 + (hsel << 3)) << 1;
                uint32_t ah0, ah1, ah2, ah3, al0, al1, al2, al3;
                ldm_x4(ah0, ah1, ah2, ah3, uAh + aoff);
                ldm_x4(al0, al1, al2, al3, uAl + aoff);
                #pragma unroll
                for (int j2 = 0; j2 < 2; ++j2) {
                    mma16816(acc[i][2*j2],   ah0, ah1, ah2, ah3, bh[j2][0], bh[j2][1]);
                    mma16816(acc[i][2*j2+1], ah0, ah1, ah2, ah3, bh[j2][2], bh[j2][3]);
                    mma16816(acc[i][2*j2],   ah0, ah1, ah2, ah3, bl[j2][0], bl[j2][1]);
                    mma16816(acc[i][2*j2+1], ah0, ah1, ah2, ah3, bl[j2][2], bl[j2][3]);
                    mma16816(acc[i][2*j2],   al0, al1, al2, al3, bh[j2][0], bh[j2][1]);
                    mma16816(acc[i][2*j2+1], al0, al1, al2, al3, bh[j2][2], bh[j2][3]);
                }
            }
        }
        __syncthreads();
    }

    int g = lane >> 2, q = lane & 3;
    #pragma unroll
    for (int i = 0; i < 4; ++i) {
        #pragma unroll
        for (int half = 0; half < 2; ++half) {
            int m = m0 + (wm << 6) + (i << 4) + g + (half << 3);
            float* dst;
            if (mode == 0) {
                dst = C + (size_t)m * N + n0;
            } else {
                int b = m >> 11, t = m & (Tt - 1), h = n0 >> 7;
                dst = C + (((size_t)(b * H + h) * Tt + t) << 7);
            }
            #pragma unroll
            for (int j = 0; j < 4; ++j) {
                int nl = (wn << 5) + (j << 3) + (q << 1);
                float2 v;
                v.x = acc[i][j][half * 2];
                v.y = acc[i][j][half * 2 + 1];
                *(float2*)(dst + nl) = v;
            }
        }
    }
}

// ---------------- RoPE (in-place on [B,H,T,HD]) ----------------
__global__ void rope_kernel(float* __restrict__ X, const float* __restrict__ cs,
                            const float* __restrict__ sn, int total)
{
    int i = blockIdx.x * blockDim.x + threadIdx.x;
    if (i >= total) return;
    int d = i & 63;
    int rest = i >> 6;
    int t = rest & (Tt - 1);
    float* row = X + ((size_t)rest << 7);
    float x1 = row[d], x2 = row[d + 64];
    float c1 = cs[(t << 7) + d],      s1 = sn[(t << 7) + d];
    float c2 = cs[(t << 7) + d + 64], s2 = sn[(t << 7) + d + 64];
    row[d]      = x1 * c1 - x2 * s1;
    row[d + 64] = x2 * c2 + x1 * s2;
}

// ========== Flash attention on mma.sync (causal, GQA, 3-term hi/lo) ========
// CTA: 256 threads (8 warps), Q tile 128 rows (16 per warp), KV tile 64.
#define FSP 136   // bf16 row stride (272B: 16B-aligned, ldmatrix conflict-free)

__global__ __launch_bounds__(256, 1) void flash_mma_kernel(
    const float* __restrict__ Q, const float* __restrict__ K,
    const float* __restrict__ V, float* __restrict__ ctx)
{
    extern __shared__ char fsm[];
    uint16_t* Qh = (uint16_t*)fsm;
    uint16_t* Ql = Qh + 128 * FSP;
    uint16_t* Kh = Ql + 128 * FSP;
    uint16_t* Kl = Kh + 64 * FSP;
    uint16_t* Vh = Kl + 64 * FSP;
    uint16_t* Vl = Vh + 64 * FSP;
    const uint32_t uQh = smem_u32(Qh), uQl = smem_u32(Ql);
    const uint32_t uKh = smem_u32(Kh), uKl = smem_u32(Kl);
    const uint32_t uVh = smem_u32(Vh), uVl = smem_u32(Vl);

    int tid = threadIdx.x, wid = tid >> 5, lane = tid & 31;
    int g = lane >> 2, qd = lane & 3;
    int r16 = lane & 15, hsel = lane >> 4;
    int qt = blockIdx.x, bh = blockIdx.y;
    int b = bh >> 4, h = bh & 15, kvh = h >> 2;

    const float* Qp = Q + (((size_t)(b * NH + h) * Tt + qt * 128) << 7);
    const float* Kp = K + (((size_t)(b * KVH + kvh) * Tt) << 7);
    const float* Vp = V + (((size_t)(b * KVH + kvh) * Tt) << 7);

    // ---- stage Q tile (128x128 fp32 -> bf16 hi/lo) ----
    {
        int row = tid >> 1, cb = (tid & 1) << 6;
        const float* qp = Qp + ((size_t)row << 7) + cb;
        #pragma unroll
        for (int i = 0; i < 16; ++i) {
            float4 v = *(const float4*)(qp + (i << 2));
            uint32_t h0, h1, l0, l1;
            split4(v, h0, h1, l0, l1);
            uint32_t off = (uint32_t)(row * FSP + cb + (i << 2)) << 1;
            *(uint32_t*)((char*)Qh + off)     = h0;
            *(uint32_t*)((char*)Qh + off + 4) = h1;
            *(uint32_t*)((char*)Ql + off)     = l0;
            *(uint32_t*)((char*)Ql + off + 4) = l1;
        }
    }

    float o[16][4];
    #pragma unroll
    for (int i = 0; i < 16; ++i)
        #pragma unroll
        for (int e = 0; e < 4; ++e) o[i][e] = 0.f;
    float m0 = -1e30f, m1 = -1e30f, l0 = 0.f, l1 = 0.f;
    const float alpha = 0.08838834764831845f * 1.4426950408889634f; // /sqrt(HD)*log2e

    int qbase = qt * 128 + wid * 16;
    int ntiles = 2 * qt + 2;

    for (int jt = 0; jt < ntiles; ++jt) {
        __syncthreads();
        // ---- stage K,V tile (64x128 fp32 -> bf16 hi/lo) ----
        {
            int row = tid >> 2, cb = (tid & 3) << 5;
            const float* kp = Kp + ((size_t)(jt * 64 + row) << 7) + cb;
            const float* vp = Vp + ((size_t)(jt * 64 + row) << 7) + cb;
            #pragma unroll
            for (int i = 0; i < 8; ++i) {
                uint32_t off = (uint32_t)(row * FSP + cb + (i << 2)) << 1;
                float4 kv = *(const float4*)(kp + (i << 2));
                uint32_t h0, h1, lo0, lo1;
                split4(kv, h0, h1, lo0, lo1);
                *(uint32_t*)((char*)Kh + off)     = h0;
                *(uint32_t*)((char*)Kh + off + 4) = h1;
                *(uint32_t*)((char*)Kl + off)     = lo0;
                *(uint32_t*)((char*)Kl + off + 4) = lo1;
                float4 vv = *(const float4*)(vp + (i << 2));
                split4(vv, h0, h1, lo0, lo1);
                *(uint32_t*)((char*)Vh + off)     = h0;
                *(uint32_t*)((char*)Vh + off + 4) = h1;
                *(uint32_t*)((char*)Vl + off)     = lo0;
                *(uint32_t*)((char*)Vl + off + 4) = lo1;
            }
        }
        __syncthreads();

        // ---- S = Q K^T (3-term hi/lo), s[8][4] frags over kv64 ----
        float s[8][4];
        #pragma unroll
        for (int t8 = 0; t8 < 8; ++t8)
            #pragma unroll
            for (int e = 0; e < 4; ++e) s[t8][e] = 0.f;

        #pragma unroll
        for (int ks = 0; ks < 8; ++ks) {
            uint32_t aoff = (uint32_t)((wid * 16 + r16) * FSP + ks * 16 + (hsel << 3)) << 1;
            uint32_t ah0, ah1, ah2, ah3, al0, al1, al2, al3;
            ldm_x4(ah0, ah1, ah2, ah3, uQh + aoff);
            ldm_x4(al0, al1, al2, al3, uQl + aoff);
            #pragma unroll
            for (int nt = 0; nt < 4; ++nt) {
                uint32_t koff = (uint32_t)((nt * 16 + r16) * FSP + ks * 16 + (hsel << 3)) << 1;
                uint32_t kh0, kh1, kh2, kh3, kl0, kl1, kl2, kl3;
                ldm_x4(kh0, kh1, kh2, kh3, uKh + koff);
                ldm_x4(kl0, kl1, kl2, kl3, uKl + koff);
                mma16816(s[2*nt],   ah0, ah1, ah2, ah3, kh0, kh2);
                mma16816(s[2*nt+1], ah0, ah1, ah2, ah3, kh1, kh3);
                mma16816(s[2*nt],   ah0, ah1, ah2, ah3, kl0, kl2);
                mma16816(s[2*nt+1], ah0, ah1, ah2, ah3, kl1, kl3);
                mma16816(s[2*nt],   al0, al1, al2, al3, kh0, kh2);
                mma16816(s[2*nt+1], al0, al1, al2, al3, kh1, kh3);
            }
        }

        // ---- scale + causal mask ----
        int kvb = jt * 64;
        int qr0 = qbase + g;
        bool needmask = (kvb + 63 > qbase);
        #pragma unroll
        for (int t8 = 0; t8 < 8; ++t8) {
            #pragma unroll
            for (int e = 0; e < 4; ++e) {
                float val = s[t8][e] * alpha;
                if (needmask) {
                    int col = kvb + t8 * 8 + qd * 2 + (e & 1);
                    int row = (e < 2) ? qr0 : qr0 + 8;
                    if (col > row) val = -1e30f;
                }
                s[t8][e] = val;
            }
        }

        // ---- online softmax (quad reductions) ----
        float tm0 = -1e30f, tm1 = -1e30f;
        #pragma unroll
        for (int t8 = 0; t8 < 8; ++t8) {
            tm0 = fmaxf(tm0, fmaxf(s[t8][0], s[t8][1]));
            tm1 = fmaxf(tm1, fmaxf(s[t8][2], s[t8][3]));
        }
        tm0 = fmaxf(tm0, __shfl_xor_sync(0xffffffffu, tm0, 1));
        tm0 = fmaxf(tm0, __shfl_xor_sync(0xffffffffu, tm0, 2));
        tm1 = fmaxf(tm1, __shfl_xor_sync(0xffffffffu, tm1, 1));
        tm1 = fmaxf(tm1, __shfl_xor_sync(0xffffffffu, tm1, 2));
        float nm0 = fmaxf(m0, tm0), nm1 = fmaxf(m1, tm1);
        float c0 = ex2(m0 - nm0), c1 = ex2(m1 - nm1);
        m0 = nm0; m1 = nm1;

        float ps0 = 0.f, ps1 = 0.f;
        #pragma unroll
        for (int t8 = 0; t8 < 8; ++t8) {
            s[t8][0] = ex2(s[t8][0] - nm0);
            s[t8][1] = ex2(s[t8][1] - nm0);
            s[t8][2] = ex2(s[t8][2] - nm1);
            s[t8][3] = ex2(s[t8][3] - nm1);
            ps0 += s[t8][0] + s[t8][1];
            ps1 += s[t8][2] + s[t8][3];
        }
        ps0 += __shfl_xor_sync(0xffffffffu, ps0, 1);
        ps0 += __shfl_xor_sync(0xffffffffu, ps0, 2);
        ps1 += __shfl_xor_sync(0xffffffffu, ps1, 1);
        ps1 += __shfl_xor_sync(0xffffffffu, ps1, 2);
        l0 = l0 * c0 + ps0;
        l1 = l1 * c1 + ps1;

        #pragma unroll
        for (int dt = 0; dt < 16; ++dt) {
            o[dt][0] *= c0; o[dt][1] *= c0;
            o[dt][2] *= c1; o[dt][3] *= c1;
        }

        // ---- O += P V (3-term hi/lo) ----
        #pragma unroll
        for (int j = 0; j < 4; ++j) {
            uint32_t ph0 = pack_hi(s[2*j][0],   s[2*j][1]);
            uint32_t ph1 = pack_hi(s[2*j][2],   s[2*j][3]);
            uint32_t ph2 = pack_hi(s[2*j+1][0], s[2*j+1][1]);
            uint32_t ph3 = pack_hi(s[2*j+1][2], s[2*j+1][3]);
            uint32_t pl0 = pack_lo(s[2*j][0],   s[2*j][1],   ph0);
            uint32_t pl1 = pack_lo(s[2*j][2],   s[2*j][3],   ph1);
            uint32_t pl2 = pack_lo(s[2*j+1][0], s[2*j+1][1], ph2);
            uint32_t pl3 = pack_lo(s[2*j+1][2], s[2*j+1][3], ph3);
            #pragma unroll
            for (int dt = 0; dt < 8; ++dt) {
                uint32_t voff = (uint32_t)((j * 16 + r16) * FSP + dt * 16 + (hsel << 3)) << 1;
                uint32_t vh0, vh1, vh2, vh3, vl0, vl1, vl2, vl3;
                ldm_x4_trans(vh0, vh1, vh2, vh3, uVh + voff);
                ldm_x4_trans(vl0, vl1, vl2, vl3, uVl + voff);
                mma16816(o[2*dt],   ph0, ph1, ph2, ph3, vh0, vh1);
                mma16816(o[2*dt+1], ph0, ph1, ph2, ph3, vh2, vh3);
                mma16816(o[2*dt],   pl0, pl1, pl2, pl3, vh0, vh1);
                mma16816(o[2*dt+1], pl0, pl1, pl2, pl3, vh2, vh3);
                mma16816(o[2*dt],   ph0, ph1, ph2, ph3, vl0, vl1);
                mma16816(o[2*dt+1], ph0, ph1, ph2, ph3, vl2, vl3);
            }
        }
    }

    // ---- finalize ----
    float li0 = 1.f / l0, li1 = 1.f / l1;
    int t0 = qbase + g;
    float* dst0 = ctx + (size_t)(b * Tt + t0) * HIDD + h * HD;
    float* dst1 = ctx + (size_t)(b * Tt + t0 + 8) * HIDD + h * HD;
    #pragma unroll
    for (int dt = 0; dt < 16; ++dt) {
        int col = dt * 8 + qd * 2;
        float2 w0 = make_float2(o[dt][0] * li0, o[dt][1] * li0);
        float2 w1 = make_float2(o[dt][2] * li1, o[dt][3] * li1);
        *(float2*)(dst0 + col) = w0;
        *(float2*)(dst1 + col) = w1;
    }
}

// ---------------- launch ----------------
extern "C" void kernel_launch(void* const* d_in, const int* in_sizes, int n_in,
                              void* d_out, int out_size)
{
    const float* hs   = (const float*)d_in[0];
    const float* cosp = (const float*)d_in[2];
    const float* sinp = (const float*)d_in[3];
    const float* Wq   = (const float*)d_in[4];
    const float* Wk   = (const float*)d_in[5];
    const float* Wv   = (const float*)d_in[6];
    const float* Wo   = (const float*)d_in[7];
    float* out = (float*)d_out;

    float *pQ, *pK, *pV, *pC;
    cudaGetSymbolAddress((void**)&pQ, g_Q);
    cudaGetSymbolAddress((void**)&pK, g_K);
    cudaGetSymbolAddress((void**)&pV, g_V);
    cudaGetSymbolAddress((void**)&pC, g_ctx);

    // QKV projections on mma.sync bf16 hi/lo
    tc_gemm_kernel<<<dim3(16, 32), 256>>>(hs, Wq, pQ, NH*HD,  HIDD, 1, NH);
    tc_gemm_kernel<<<dim3(4,  32), 256>>>(hs, Wk, pK, KVH*HD, HIDD, 1, KVH);
    tc_gemm_kernel<<<dim3(4,  32), 256>>>(hs, Wv, pV, KVH*HD, HIDD, 1, KVH);

    // RoPE on Q and K
    int totQ = Bb * NH  * Tt * 64;
    int totK = Bb * KVH * Tt * 64;
    rope_kernel<<<totQ / 256, 256>>>(pQ, cosp, sinp, totQ);
    rope_kernel<<<totK / 256, 256>>>(pK, cosp, sinp, totK);

    // Flash attention on mma.sync
    size_t fsh = (size_t)(2 * 128 * FSP + 4 * 64 * FSP) * sizeof(uint16_t); // 139264
    cudaFuncSetAttribute(flash_mma_kernel, cudaFuncAttributeMaxDynamicSharedMemorySize, (int)fsh);
    flash_mma_kernel<<<dim3(Tt/128, Bb*NH), 256, fsh>>>(pQ, pK, pV, pC);

    // Output projection -> d_out
    tc_gemm_kernel<<<dim3(16, 32), 256>>>(pC, Wo, out, HIDD, HIDD, 0, 0);
}